// round 3
// baseline (speedup 1.0000x reference)
#include <cuda_runtime.h>

#define D_MODEL 128
#define C_FEAT  16
#define LN_EPS  1e-5f

// Packed per-node xy for both batches: {x_b0, y_b0, x_b1, y_b1}.
// 50000 nodes * 16B = 800KB -> fully L2-resident gather table.
#define N_NODES 50000
__device__ float4 g_xy[N_NODES];

// Runtime-detected index dtype: 1 if edge_index buffer is int32, 0 if int64.
__device__ int g_is32;

// ---------------------------------------------------------------------------
// Dtype detector. Reference dtype is int64 with values < 50000, so when the
// buffer really holds int64, every high 32-bit word is zero. If the harness
// materialized it as int32, the "high words" are random indices (nonzero with
// overwhelming probability over 256 samples). Deterministic: same input ->
// same flag.
// ---------------------------------------------------------------------------
__global__ void detect_kernel(const int* __restrict__ ei32) {
    if (threadIdx.x == 0 && blockIdx.x == 0) {
        int f = 0;
        for (int i = 1; i < 512; i += 2) f |= ei32[i];
        g_is32 = (f != 0) ? 1 : 0;
    }
}

// ---------------------------------------------------------------------------
// Encoder: one warp per row r = b*N + n.
//   h = GELU(static[r] @ W + bias)   (exact erf GELU)
//   H0[r] = LayerNorm(h) * gamma + beta
// Side effect: lane 0 stashes (static[r][0], static[r][1]) into g_xy[n]
// at the half selected by b, building the packed gather table for kernel 2.
// ---------------------------------------------------------------------------
__global__ void encoder_kernel(const float* __restrict__ x,
                               const float* __restrict__ W,
                               const float* __restrict__ bias,
                               const float* __restrict__ gamma,
                               const float* __restrict__ beta,
                               float* __restrict__ out,
                               int rows, int n_nodes) {
    __shared__ float sW[C_FEAT * D_MODEL];
    __shared__ float sb[D_MODEL];
    __shared__ float sg[D_MODEL];
    __shared__ float sbe[D_MODEL];

    for (int i = threadIdx.x; i < C_FEAT * D_MODEL; i += blockDim.x)
        sW[i] = W[i];
    if (threadIdx.x < D_MODEL) {
        sb[threadIdx.x]  = bias[threadIdx.x];
        sg[threadIdx.x]  = gamma[threadIdx.x];
        sbe[threadIdx.x] = beta[threadIdx.x];
    }
    __syncthreads();

    int warp = threadIdx.x >> 5;
    int lane = threadIdx.x & 31;
    int r = blockIdx.x * (blockDim.x >> 5) + warp;
    if (r >= rows) return;

    // Load the 16 input features as 4 x float4 (broadcast across the warp).
    const float4* row4 = reinterpret_cast<const float4*>(x + (size_t)r * C_FEAT);
    float sv[C_FEAT];
#pragma unroll
    for (int q = 0; q < 4; q++) {
        float4 f = __ldg(row4 + q);
        sv[4 * q + 0] = f.x; sv[4 * q + 1] = f.y;
        sv[4 * q + 2] = f.z; sv[4 * q + 3] = f.w;
    }

    // Stash packed xy for the edge kernel.
    if (lane == 0) {
        int b = (r >= n_nodes) ? 1 : 0;
        int n = r - b * n_nodes;
        if (n >= 0 && n < N_NODES) {
            float2* p = reinterpret_cast<float2*>(
                reinterpret_cast<char*>(&g_xy[n]) + (size_t)b * 8);
            *p = make_float2(sv[0], sv[1]);
        }
    }

    // Each lane computes 4 output channels: d = lane + 32*j.
    float v[4];
    float sum = 0.f, sumsq = 0.f;
#pragma unroll
    for (int j = 0; j < 4; j++) {
        int d = lane + 32 * j;
        float acc = sb[d];
#pragma unroll
        for (int c = 0; c < C_FEAT; c++)
            acc = fmaf(sv[c], sW[c * D_MODEL + d], acc);
        // exact-erf GELU
        float gel = 0.5f * acc * (1.0f + erff(acc * 0.70710678118654752f));
        v[j] = gel;
        sum += gel;
        sumsq += gel * gel;
    }

    // Warp reduction over 128 values (4 per lane).
#pragma unroll
    for (int o = 16; o > 0; o >>= 1) {
        sum   += __shfl_xor_sync(0xFFFFFFFFu, sum, o);
        sumsq += __shfl_xor_sync(0xFFFFFFFFu, sumsq, o);
    }
    float mean = sum * (1.0f / D_MODEL);
    float var  = sumsq * (1.0f / D_MODEL) - mean * mean;
    float rstd = rsqrtf(var + LN_EPS);

    float* orow = out + (size_t)r * D_MODEL;
#pragma unroll
    for (int j = 0; j < 4; j++) {
        int d = lane + 32 * j;
        orow[d] = (v[j] - mean) * rstd * sg[d] + sbe[d];
    }
}

// ---------------------------------------------------------------------------
// Edge deterrence: one thread handles TWO consecutive edges, BOTH batches.
//   det[b*E + e] = -0.5 * || xy[b*N + src[e]] - xy[b*N + dst[e]] ||^2
// Both batches' coords are packed in one float4 -> 2 gathers per edge.
// Index dtype selected at runtime via g_is32 (uniform branch). All gather
// indices clamped to [0, n_nodes) so a bad assumption yields a rel_err
// diagnostic, never an illegal access.
// ---------------------------------------------------------------------------
__global__ void edge_kernel(const void* __restrict__ ei_raw,
                            float* __restrict__ det, int E, int n_nodes) {
    int p = blockIdx.x * blockDim.x + threadIdx.x;   // pair index
    int e = p * 2;
    if (e >= E) return;
    bool full = (e + 1 < E);

    unsigned s0, s1, d0, d1;
    if (g_is32) {
        const int* e32 = (const int*)ei_raw;
        if (full) {
            int2 sp = __ldg(reinterpret_cast<const int2*>(e32 + e));
            int2 dp = __ldg(reinterpret_cast<const int2*>(e32 + (size_t)E + e));
            s0 = (unsigned)sp.x; s1 = (unsigned)sp.y;
            d0 = (unsigned)dp.x; d1 = (unsigned)dp.y;
        } else {
            s0 = (unsigned)__ldg(e32 + e);            s1 = 0;
            d0 = (unsigned)__ldg(e32 + (size_t)E + e); d1 = 0;
        }
    } else {
        const long long* e64 = (const long long*)ei_raw;
        if (full) {
            longlong2 sp = __ldg(reinterpret_cast<const longlong2*>(e64 + e));
            longlong2 dp = __ldg(reinterpret_cast<const longlong2*>(e64 + (size_t)E + e));
            s0 = (unsigned)sp.x; s1 = (unsigned)sp.y;
            d0 = (unsigned)dp.x; d1 = (unsigned)dp.y;
        } else {
            s0 = (unsigned)__ldg(e64 + e);            s1 = 0;
            d0 = (unsigned)__ldg(e64 + (size_t)E + e); d1 = 0;
        }
    }

    unsigned lim = (unsigned)(n_nodes - 1);
    s0 = min(s0, lim); s1 = min(s1, lim);
    d0 = min(d0, lim); d1 = min(d1, lim);

    float4 ps0 = __ldg(&g_xy[s0]);
    float4 pd0 = __ldg(&g_xy[d0]);
    float4 ps1 = __ldg(&g_xy[s1]);
    float4 pd1 = __ldg(&g_xy[d1]);

    float dx, dy;
    float r0x, r0y, r1x, r1y;
    dx = ps0.x - pd0.x; dy = ps0.y - pd0.y; r0x = -0.5f * (dx * dx + dy * dy);
    dx = ps1.x - pd1.x; dy = ps1.y - pd1.y; r0y = -0.5f * (dx * dx + dy * dy);
    dx = ps0.z - pd0.z; dy = ps0.w - pd0.w; r1x = -0.5f * (dx * dx + dy * dy);
    dx = ps1.z - pd1.z; dy = ps1.w - pd1.w; r1y = -0.5f * (dx * dx + dy * dy);

    if (full) {
        *reinterpret_cast<float2*>(det + e) = make_float2(r0x, r0y);
        *reinterpret_cast<float2*>(det + (size_t)E + e) = make_float2(r1x, r1y);
    } else {
        det[e] = r0x;
        det[(size_t)E + e] = r1x;
    }
}

// ---------------------------------------------------------------------------
// Launch. Inputs (metadata order): static, edge_index, fc_w, fc_b, ln_g, ln_b
// Output: [H0 flat (rows*128 f32)] ++ [det flat (2*E f32)]
// E is derived from out_size (robust to the element-counting convention of
// the int64 edge_index buffer): out_size = rows*128 + 2*E.
// ---------------------------------------------------------------------------
extern "C" void kernel_launch(void* const* d_in, const int* in_sizes, int n_in,
                              void* d_out, int out_size) {
    const float* x    = (const float*)d_in[0];
    const void*  ei   = d_in[1];
    const float* W    = (const float*)d_in[2];
    const float* bias = (const float*)d_in[3];
    const float* g    = (const float*)d_in[4];
    const float* be   = (const float*)d_in[5];

    int rows    = in_sizes[0] / C_FEAT;                    // B*N = 100000
    int n_nodes = rows / 2;                                // N = 50000 (B=2)
    long long detN = (long long)out_size - (long long)rows * D_MODEL; // B*E
    int E = (int)(detN / 2);                               // 1600000

    float* H0  = (float*)d_out;
    float* det = (float*)d_out + (size_t)rows * D_MODEL;

    detect_kernel<<<1, 32>>>((const int*)ei);

    // 256 threads = 8 warps = 8 rows per block.
    int nblk = (rows + 7) / 8;
    encoder_kernel<<<nblk, 256>>>(x, W, bias, g, be, H0, rows, n_nodes);

    // 2 edges per thread.
    int npair = (E + 1) / 2;
    edge_kernel<<<(npair + 255) / 256, 256>>>(ei, det, E, n_nodes);
}

// round 4
// speedup vs baseline: 1.0672x; 1.0672x over previous
#include <cuda_runtime.h>

#define D_MODEL 128
#define C_FEAT  16
#define LN_EPS  1e-5f

// Packed per-node xy for both batches: {x_b0, y_b0, x_b1, y_b1}.
// 50000 nodes * 16B = 800KB -> fully L2-resident gather table.
#define N_NODES 50000
__device__ float4 g_xy[N_NODES];

// Runtime-detected index dtype: 1 if edge_index buffer is int32, 0 if int64.
__device__ int g_is32;

// ---------------------------------------------------------------------------
// Dtype detector (parallel). Reference dtype is int64 with values < 50000:
// if the buffer is genuine int64, every high 32-bit word is zero. If it was
// materialized as int32, those positions hold random indices (nonzero over
// 256 samples with overwhelming probability). 32 threads x 8 independent
// loads -> one DRAM round trip instead of 256 serialized ones.
// ---------------------------------------------------------------------------
__global__ void detect_kernel(const int* __restrict__ ei32) {
    int f = 0;
#pragma unroll
    for (int i = 0; i < 8; i++)
        f |= __ldg(ei32 + ((threadIdx.x * 8 + i) * 2 + 1));
    unsigned any = __ballot_sync(0xFFFFFFFFu, f != 0);
    if (threadIdx.x == 0) g_is32 = (any != 0) ? 1 : 0;
}

// ---------------------------------------------------------------------------
// Encoder: one warp per row r = b*N + n.
//   h = GELU(static[r] @ W + bias)   (exact erf GELU)
//   H0[r] = LayerNorm(h) * gamma + beta
// Rows are staged cooperatively: a block's 8 rows = 128 contiguous floats,
// one coalesced load into smem (instead of 32x redundant broadcast LDGs).
// Side effect: lane 0 stashes (static[r][0], static[r][1]) into g_xy[n],
// building the packed gather table for the edge kernel.
// ---------------------------------------------------------------------------
__global__ void __launch_bounds__(256) encoder_kernel(
        const float* __restrict__ x,
        const float* __restrict__ W,
        const float* __restrict__ bias,
        const float* __restrict__ gamma,
        const float* __restrict__ beta,
        float* __restrict__ out,
        int rows, int n_nodes) {
    __shared__ float sW[C_FEAT * D_MODEL];
    __shared__ float sb[D_MODEL];
    __shared__ float sg[D_MODEL];
    __shared__ float sbe[D_MODEL];
    __shared__ float sRow[8 * C_FEAT];     // 8 rows x 16 features

    for (int i = threadIdx.x; i < C_FEAT * D_MODEL; i += blockDim.x)
        sW[i] = W[i];
    if (threadIdx.x < D_MODEL) {
        sb[threadIdx.x]  = bias[threadIdx.x];
        sg[threadIdx.x]  = gamma[threadIdx.x];
        sbe[threadIdx.x] = beta[threadIdx.x];
    }
    {   // coalesced row staging: 128 consecutive floats from x
        int gbase = blockIdx.x * 8 * C_FEAT;
        if (threadIdx.x < 8 * C_FEAT) {
            int gi = gbase + threadIdx.x;
            sRow[threadIdx.x] = (gi < rows * C_FEAT) ? x[gi] : 0.f;
        }
    }
    __syncthreads();

    int warp = threadIdx.x >> 5;
    int lane = threadIdx.x & 31;
    int r = blockIdx.x * 8 + warp;
    if (r >= rows) return;

    float sv[C_FEAT];
#pragma unroll
    for (int c = 0; c < C_FEAT; c++) sv[c] = sRow[warp * C_FEAT + c];

    // Stash packed xy for the edge kernel.
    if (lane == 0) {
        int b = (r >= n_nodes) ? 1 : 0;
        int n = r - b * n_nodes;
        if (n >= 0 && n < N_NODES) {
            float2* p = reinterpret_cast<float2*>(
                reinterpret_cast<char*>(&g_xy[n]) + (size_t)b * 8);
            *p = make_float2(sv[0], sv[1]);
        }
    }

    // Each lane computes 4 output channels: d = lane + 32*j.
    float v[4];
    float sum = 0.f, sumsq = 0.f;
#pragma unroll
    for (int j = 0; j < 4; j++) {
        int d = lane + 32 * j;
        float acc = sb[d];
#pragma unroll
        for (int c = 0; c < C_FEAT; c++)
            acc = fmaf(sv[c], sW[c * D_MODEL + d], acc);
        // exact-erf GELU
        float gel = 0.5f * acc * (1.0f + erff(acc * 0.70710678118654752f));
        v[j] = gel;
        sum += gel;
        sumsq += gel * gel;
    }

    // Warp reduction over 128 values (4 per lane).
#pragma unroll
    for (int o = 16; o > 0; o >>= 1) {
        sum   += __shfl_xor_sync(0xFFFFFFFFu, sum, o);
        sumsq += __shfl_xor_sync(0xFFFFFFFFu, sumsq, o);
    }
    float mean = sum * (1.0f / D_MODEL);
    float var  = sumsq * (1.0f / D_MODEL) - mean * mean;
    float rstd = rsqrtf(var + LN_EPS);

    float* orow = out + (size_t)r * D_MODEL;
#pragma unroll
    for (int j = 0; j < 4; j++) {
        int d = lane + 32 * j;
        orow[d] = (v[j] - mean) * rstd * sg[d] + sbe[d];
    }
}

// ---------------------------------------------------------------------------
// Edge deterrence: one thread handles FOUR consecutive edges, BOTH batches.
//   det[b*E + e] = -0.5 * || xy[b*N + src[e]] - xy[b*N + dst[e]] ||^2
// Both batches' coords packed in one float4 -> 2 gathers per edge; 8
// independent gathers in flight per thread. Index dtype chosen at runtime
// via g_is32 (uniform branch). Indices clamped to [0, n_nodes) so a bad
// assumption yields a rel_err diagnostic, never an illegal access.
// ---------------------------------------------------------------------------
__global__ void __launch_bounds__(256) edge_kernel(
        const void* __restrict__ ei_raw,
        float* __restrict__ det, int E, int n_nodes) {
    int q = blockIdx.x * blockDim.x + threadIdx.x;
    int e = q * 4;
    if (e >= E) return;

    unsigned s[4], d[4];
    bool full = (e + 3 < E);
    if (full) {
        if (g_is32) {
            const int* p = (const int*)ei_raw;
            int4 a = __ldg(reinterpret_cast<const int4*>(p + e));
            int4 b = __ldg(reinterpret_cast<const int4*>(p + (size_t)E + e));
            s[0] = a.x; s[1] = a.y; s[2] = a.z; s[3] = a.w;
            d[0] = b.x; d[1] = b.y; d[2] = b.z; d[3] = b.w;
        } else {
            const long long* p = (const long long*)ei_raw;
            longlong2 a0 = __ldg(reinterpret_cast<const longlong2*>(p + e));
            longlong2 a1 = __ldg(reinterpret_cast<const longlong2*>(p + e + 2));
            longlong2 b0 = __ldg(reinterpret_cast<const longlong2*>(p + (size_t)E + e));
            longlong2 b1 = __ldg(reinterpret_cast<const longlong2*>(p + (size_t)E + e + 2));
            s[0] = (unsigned)a0.x; s[1] = (unsigned)a0.y;
            s[2] = (unsigned)a1.x; s[3] = (unsigned)a1.y;
            d[0] = (unsigned)b0.x; d[1] = (unsigned)b0.y;
            d[2] = (unsigned)b1.x; d[3] = (unsigned)b1.y;
        }
    } else {
#pragma unroll
        for (int k = 0; k < 4; k++) {
            if (e + k < E) {
                if (g_is32) {
                    const int* p = (const int*)ei_raw;
                    s[k] = (unsigned)__ldg(p + e + k);
                    d[k] = (unsigned)__ldg(p + (size_t)E + e + k);
                } else {
                    const long long* p = (const long long*)ei_raw;
                    s[k] = (unsigned)__ldg(p + e + k);
                    d[k] = (unsigned)__ldg(p + (size_t)E + e + k);
                }
            } else { s[k] = 0; d[k] = 0; }
        }
    }

    unsigned lim = (unsigned)(n_nodes - 1);
    float4 ps[4], pd[4];
#pragma unroll
    for (int k = 0; k < 4; k++) {
        ps[k] = __ldg(&g_xy[min(s[k], lim)]);
        pd[k] = __ldg(&g_xy[min(d[k], lim)]);
    }

    float r0[4], r1[4];
#pragma unroll
    for (int k = 0; k < 4; k++) {
        float dx0 = ps[k].x - pd[k].x, dy0 = ps[k].y - pd[k].y;
        float dx1 = ps[k].z - pd[k].z, dy1 = ps[k].w - pd[k].w;
        r0[k] = -0.5f * (dx0 * dx0 + dy0 * dy0);
        r1[k] = -0.5f * (dx1 * dx1 + dy1 * dy1);
    }

    if (full) {
        *reinterpret_cast<float4*>(det + e) =
            make_float4(r0[0], r0[1], r0[2], r0[3]);
        *reinterpret_cast<float4*>(det + (size_t)E + e) =
            make_float4(r1[0], r1[1], r1[2], r1[3]);
    } else {
#pragma unroll
        for (int k = 0; k < 4; k++) {
            if (e + k < E) {
                det[e + k] = r0[k];
                det[(size_t)E + e + k] = r1[k];
            }
        }
    }
}

// ---------------------------------------------------------------------------
// Launch. Inputs (metadata order): static, edge_index, fc_w, fc_b, ln_g, ln_b
// Output: [H0 flat (rows*128 f32)] ++ [det flat (2*E f32)]
// E derived from out_size (robust to the element-counting convention of the
// int64 edge_index buffer): out_size = rows*128 + 2*E.
// ---------------------------------------------------------------------------
extern "C" void kernel_launch(void* const* d_in, const int* in_sizes, int n_in,
                              void* d_out, int out_size) {
    const float* x    = (const float*)d_in[0];
    const void*  ei   = d_in[1];
    const float* W    = (const float*)d_in[2];
    const float* bias = (const float*)d_in[3];
    const float* g    = (const float*)d_in[4];
    const float* be   = (const float*)d_in[5];

    int rows    = in_sizes[0] / C_FEAT;                    // B*N = 100000
    int n_nodes = rows / 2;                                // N = 50000 (B=2)
    long long detN = (long long)out_size - (long long)rows * D_MODEL; // B*E
    int E = (int)(detN / 2);                               // 1600000

    float* H0  = (float*)d_out;
    float* det = (float*)d_out + (size_t)rows * D_MODEL;

    detect_kernel<<<1, 32>>>((const int*)ei);

    int nblk = (rows + 7) / 8;                 // 8 rows per 256-thread block
    encoder_kernel<<<nblk, 256>>>(x, W, bias, g, be, H0, rows, n_nodes);

    int nquad = (E + 3) / 4;                   // 4 edges per thread
    edge_kernel<<<(nquad + 255) / 256, 256>>>(ei, det, E, n_nodes);
}

// round 6
// speedup vs baseline: 1.0936x; 1.0247x over previous
#include <cuda_runtime.h>

#define D_MODEL 128
#define C_FEAT  16
#define LN_EPS  1e-5f

// Packed per-node xy for both batches: {x_b0, y_b0, x_b1, y_b1}.
// 50000 nodes * 16B = 800KB -> fully L2-resident gather table.
#define N_NODES 50000
__device__ float4 g_xy[N_NODES];

// Runtime-detected index dtype: 1 if edge_index buffer is int32, 0 if int64.
__device__ int g_is32;

// ---------------------------------------------------------------------------
// Fast exact-enough GELU. erf via Abramowitz-Stegun 7.1.26 (|abs err|<=1.5e-7)
//   erf(t) = 1 - (a1 k + ... + a5 k^5) e^{-t^2},  k = 1/(1+p t),  t >= 0
// gelu(x) = 0.5 x (1 + erf(x/sqrt2)) = 0.5 x + 0.5 |x| erfabs   (sign folds)
// Branch-free, ~12 instructions vs ~25-30 for libm erff.
// ---------------------------------------------------------------------------
__device__ __forceinline__ float fast_gelu(float x) {
    float ax = fabsf(x);
    float t = ax * 0.70710678118654752f;
    float k = __fdividef(1.0f, fmaf(0.3275911f, t, 1.0f));
    float p = fmaf(1.061405429f, k, -1.453152027f);
    p = fmaf(p, k, 1.421413741f);
    p = fmaf(p, k, -0.284496736f);
    p = fmaf(p, k, 0.254829592f);
    p *= k;
    float erfabs = 1.0f - p * __expf(-t * t);
    return fmaf(0.5f * ax, erfabs, 0.5f * x);
}

// ---------------------------------------------------------------------------
// Encoder: one warp per row r = b*N + n.
//   h = GELU(static[r] @ W + bias);  H0[r] = LayerNorm(h) * gamma + beta
// The LAST block (blockIdx.x == gridDim.x-1) instead runs the index-dtype
// detector with one warp: if the edge_index buffer is genuine int64 (values
// < 50000), every high 32-bit word is zero; if it was materialized as int32
// those words hold random indices (nonzero over 256 samples whp).
// Side effect: lane 0 stashes (static[r][0], static[r][1]) into g_xy[n],
// building the packed gather table for the edge kernel.
// ---------------------------------------------------------------------------
__global__ void __launch_bounds__(256) encoder_kernel(
        const float* __restrict__ x,
        const int*   __restrict__ ei32,
        const float* __restrict__ W,
        const float* __restrict__ bias,
        const float* __restrict__ gamma,
        const float* __restrict__ beta,
        float* __restrict__ out,
        int rows, int n_nodes) {
    if (blockIdx.x == gridDim.x - 1) {            // detector block
        if (threadIdx.x < 32) {
            int f = 0;
#pragma unroll
            for (int i = 0; i < 8; i++)
                f |= __ldg(ei32 + ((threadIdx.x * 8 + i) * 2 + 1));
            unsigned any = __ballot_sync(0xFFFFFFFFu, f != 0);
            if (threadIdx.x == 0) g_is32 = (any != 0) ? 1 : 0;
        }
        return;
    }

    __shared__ float sW[C_FEAT * D_MODEL];
    __shared__ float sb[D_MODEL];
    __shared__ float sg[D_MODEL];
    __shared__ float sbe[D_MODEL];
    __shared__ float sRow[8 * C_FEAT];            // 8 rows x 16 features

    for (int i = threadIdx.x; i < C_FEAT * D_MODEL; i += blockDim.x)
        sW[i] = W[i];
    if (threadIdx.x < D_MODEL) {
        sb[threadIdx.x]  = bias[threadIdx.x];
        sg[threadIdx.x]  = gamma[threadIdx.x];
        sbe[threadIdx.x] = beta[threadIdx.x];
    }
    {   // coalesced row staging: 128 consecutive floats from x
        int gbase = blockIdx.x * 8 * C_FEAT;
        if (threadIdx.x < 8 * C_FEAT) {
            int gi = gbase + threadIdx.x;
            sRow[threadIdx.x] = (gi < rows * C_FEAT) ? x[gi] : 0.f;
        }
    }
    __syncthreads();

    int warp = threadIdx.x >> 5;
    int lane = threadIdx.x & 31;
    int r = blockIdx.x * 8 + warp;
    if (r >= rows) return;

    float sv[C_FEAT];
#pragma unroll
    for (int c = 0; c < C_FEAT; c++) sv[c] = sRow[warp * C_FEAT + c];

    // Stash packed xy for the edge kernel.
    if (lane == 0) {
        int b = (r >= n_nodes) ? 1 : 0;
        int n = r - b * n_nodes;
        if (n >= 0 && n < N_NODES) {
            float2* p = reinterpret_cast<float2*>(
                reinterpret_cast<char*>(&g_xy[n]) + (size_t)b * 8);
            *p = make_float2(sv[0], sv[1]);
        }
    }

    // Each lane computes 4 output channels: d = lane + 32*j.
    float v[4];
    float sum = 0.f, sumsq = 0.f;
#pragma unroll
    for (int j = 0; j < 4; j++) {
        int d = lane + 32 * j;
        float acc = sb[d];
#pragma unroll
        for (int c = 0; c < C_FEAT; c++)
            acc = fmaf(sv[c], sW[c * D_MODEL + d], acc);
        float gel = fast_gelu(acc);
        v[j] = gel;
        sum += gel;
        sumsq += gel * gel;
    }

    // Warp reduction over 128 values (4 per lane).
#pragma unroll
    for (int o = 16; o > 0; o >>= 1) {
        sum   += __shfl_xor_sync(0xFFFFFFFFu, sum, o);
        sumsq += __shfl_xor_sync(0xFFFFFFFFu, sumsq, o);
    }
    float mean = sum * (1.0f / D_MODEL);
    float var  = sumsq * (1.0f / D_MODEL) - mean * mean;
    float rstd = rsqrtf(var + LN_EPS);

    float* orow = out + (size_t)r * D_MODEL;
#pragma unroll
    for (int j = 0; j < 4; j++) {
        int d = lane + 32 * j;
        orow[d] = (v[j] - mean) * rstd * sg[d] + sbe[d];
    }
}

// ---------------------------------------------------------------------------
// Edge deterrence: one thread handles FOUR consecutive edges, BOTH batches.
//   det[b*E + e] = -0.5 * || xy[b*N + src[e]] - xy[b*N + dst[e]] ||^2
// Both batches' coords packed in one float4 -> 2 gathers per edge; 8
// independent gathers in flight per thread. Index dtype chosen at runtime
// via g_is32 (uniform branch). Indices clamped to [0, n_nodes) so a bad
// assumption yields a rel_err diagnostic, never an illegal access.
// ---------------------------------------------------------------------------
__global__ void __launch_bounds__(256) edge_kernel(
        const void* __restrict__ ei_raw,
        float* __restrict__ det, int E, int n_nodes) {
    int q = blockIdx.x * blockDim.x + threadIdx.x;
    int e = q * 4;
    if (e >= E) return;

    unsigned s[4], d[4];
    bool full = (e + 3 < E);
    if (full) {
        if (g_is32) {
            const int* p = (const int*)ei_raw;
            int4 a = __ldg(reinterpret_cast<const int4*>(p + e));
            int4 b = __ldg(reinterpret_cast<const int4*>(p + (size_t)E + e));
            s[0] = a.x; s[1] = a.y; s[2] = a.z; s[3] = a.w;
            d[0] = b.x; d[1] = b.y; d[2] = b.z; d[3] = b.w;
        } else {
            const long long* p = (const long long*)ei_raw;
            longlong2 a0 = __ldg(reinterpret_cast<const longlong2*>(p + e));
            longlong2 a1 = __ldg(reinterpret_cast<const longlong2*>(p + e + 2));
            longlong2 b0 = __ldg(reinterpret_cast<const longlong2*>(p + (size_t)E + e));
            longlong2 b1 = __ldg(reinterpret_cast<const longlong2*>(p + (size_t)E + e + 2));
            s[0] = (unsigned)a0.x; s[1] = (unsigned)a0.y;
            s[2] = (unsigned)a1.x; s[3] = (unsigned)a1.y;
            d[0] = (unsigned)b0.x; d[1] = (unsigned)b0.y;
            d[2] = (unsigned)b1.x; d[3] = (unsigned)b1.y;
        }
    } else {
#pragma unroll
        for (int k = 0; k < 4; k++) {
            if (e + k < E) {
                if (g_is32) {
                    const int* p = (const int*)ei_raw;
                    s[k] = (unsigned)__ldg(p + e + k);
                    d[k] = (unsigned)__ldg(p + (size_t)E + e + k);
                } else {
                    const long long* p = (const long long*)ei_raw;
                    s[k] = (unsigned)__ldg(p + e + k);
                    d[k] = (unsigned)__ldg(p + (size_t)E + e + k);
                }
            } else { s[k] = 0; d[k] = 0; }
        }
    }

    unsigned lim = (unsigned)(n_nodes - 1);
    float4 ps[4], pd[4];
#pragma unroll
    for (int k = 0; k < 4; k++) {
        ps[k] = __ldg(&g_xy[min(s[k], lim)]);
        pd[k] = __ldg(&g_xy[min(d[k], lim)]);
    }

    float r0[4], r1[4];
#pragma unroll
    for (int k = 0; k < 4; k++) {
        float dx0 = ps[k].x - pd[k].x, dy0 = ps[k].y - pd[k].y;
        float dx1 = ps[k].z - pd[k].z, dy1 = ps[k].w - pd[k].w;
        r0[k] = -0.5f * (dx0 * dx0 + dy0 * dy0);
        r1[k] = -0.5f * (dx1 * dx1 + dy1 * dy1);
    }

    if (full) {
        *reinterpret_cast<float4*>(det + e) =
            make_float4(r0[0], r0[1], r0[2], r0[3]);
        *reinterpret_cast<float4*>(det + (size_t)E + e) =
            make_float4(r1[0], r1[1], r1[2], r1[3]);
    } else {
#pragma unroll
        for (int k = 0; k < 4; k++) {
            if (e + k < E) {
                det[e + k] = r0[k];
                det[(size_t)E + e + k] = r1[k];
            }
        }
    }
}

// ---------------------------------------------------------------------------
// Launch. Inputs (metadata order): static, edge_index, fc_w, fc_b, ln_g, ln_b
// Output: [H0 flat (rows*128 f32)] ++ [det flat (2*E f32)]
// E derived from out_size (robust to the element-counting convention of the
// int64 edge_index buffer): out_size = rows*128 + 2*E.
// ---------------------------------------------------------------------------
extern "C" void kernel_launch(void* const* d_in, const int* in_sizes, int n_in,
                              void* d_out, int out_size) {
    const float* x    = (const float*)d_in[0];
    const void*  ei   = d_in[1];
    const float* W    = (const float*)d_in[2];
    const float* bias = (const float*)d_in[3];
    const float* g    = (const float*)d_in[4];
    const float* be   = (const float*)d_in[5];

    int rows    = in_sizes[0] / C_FEAT;                    // B*N = 100000
    int n_nodes = rows / 2;                                // N = 50000 (B=2)
    long long detN = (long long)out_size - (long long)rows * D_MODEL; // B*E
    int E = (int)(detN / 2);                               // 1600000

    float* H0  = (float*)d_out;
    float* det = (float*)d_out + (size_t)rows * D_MODEL;

    // +1 block: the last block runs the index-dtype detector.
    int nblk = (rows + 7) / 8 + 1;             // 8 rows per 256-thread block
    encoder_kernel<<<nblk, 256>>>(x, (const int*)ei, W, bias, g, be, H0,
                                  rows, n_nodes);

    int nquad = (E + 3) / 4;                   // 4 edges per thread
    edge_kernel<<<(nquad + 255) / 256, 256>>>(ei, det, E, n_nodes);
}

// round 7
// speedup vs baseline: 1.4545x; 1.3301x over previous
#include <cuda_runtime.h>

#define D_MODEL 128
#define C_FEAT  16
#define LN_EPS  1e-5f
#define ROWS_PER_BLOCK 128
#define ROWS_PER_WARP  16

// Packed per-node xy for both batches: {x_b0, y_b0, x_b1, y_b1}.
// 50000 nodes * 16B = 800KB -> fully L2-resident gather table.
#define N_NODES 50000
__device__ float4 g_xy[N_NODES];

// Runtime-detected index dtype: 1 if edge_index buffer is int32, 0 if int64.
__device__ int g_is32;

// ---------------------------------------------------------------------------
// Fast exact-enough GELU. erf via Abramowitz-Stegun 7.1.26 (|abs err|<=1.5e-7)
// gelu(x) = 0.5 x (1 + erf(x/sqrt2)) = 0.5 x + 0.5|x| erf(|x|/sqrt2)
// ---------------------------------------------------------------------------
__device__ __forceinline__ float fast_gelu(float x) {
    float ax = fabsf(x);
    float t = ax * 0.70710678118654752f;
    float k = __fdividef(1.0f, fmaf(0.3275911f, t, 1.0f));
    float p = fmaf(1.061405429f, k, -1.453152027f);
    p = fmaf(p, k, 1.421413741f);
    p = fmaf(p, k, -0.284496736f);
    p = fmaf(p, k, 0.254829592f);
    p *= k;
    float erfabs = 1.0f - p * __expf(-t * t);
    return fmaf(0.5f * ax, erfabs, 0.5f * x);
}

// ---------------------------------------------------------------------------
// Encoder v2: REGISTER-RESIDENT WEIGHTS.
// Each lane owns 4 consecutive output channels d = 4*lane .. 4*lane+3 and
// keeps W[:, d:d+4] in 16 float4 registers (row-invariant). Each warp then
// loops over 16 rows; per row only 16 smem broadcasts (sv) + reg-reg FMAs +
// GELU + LN + one STG.128. This removes the 64 weight-LDS per row that made
// v1 smem-crossbar bound (~48us).
// The LAST block runs the index-dtype detector (one warp): genuine int64
// indices < 50000 have all-zero high words; int32-materialized data doesn't.
// Side effect: lane 0 stashes (sv[0], sv[1]) into g_xy[n] for the edge kernel.
// ---------------------------------------------------------------------------
__global__ void __launch_bounds__(256, 2) encoder_kernel(
        const float* __restrict__ x,
        const int*   __restrict__ ei32,
        const float* __restrict__ W,
        const float* __restrict__ bias,
        const float* __restrict__ gamma,
        const float* __restrict__ beta,
        float* __restrict__ out,
        int rows, int n_nodes) {
    if (blockIdx.x == gridDim.x - 1) {            // detector block
        if (threadIdx.x < 32) {
            int f = 0;
#pragma unroll
            for (int i = 0; i < 8; i++)
                f |= __ldg(ei32 + ((threadIdx.x * 8 + i) * 2 + 1));
            unsigned any = __ballot_sync(0xFFFFFFFFu, f != 0);
            if (threadIdx.x == 0) g_is32 = (any != 0) ? 1 : 0;
        }
        return;
    }

    __shared__ float sRow[ROWS_PER_BLOCK * C_FEAT];   // 8KB: 128 rows staged

    int base = blockIdx.x * ROWS_PER_BLOCK;
    // Coalesced staging of this block's rows (guarded scalar for the tail).
    {
        int gbase = base * C_FEAT;
        int total = rows * C_FEAT;
#pragma unroll
        for (int i = 0; i < ROWS_PER_BLOCK * C_FEAT / 256; i++) {
            int li = threadIdx.x + i * 256;
            int gi = gbase + li;
            sRow[li] = (gi < total) ? x[gi] : 0.f;
        }
    }

    int warp = threadIdx.x >> 5;
    int lane = threadIdx.x & 31;

    // Register-resident weights/affine params for channels 4*lane..4*lane+3.
    float4 w[C_FEAT];
#pragma unroll
    for (int c = 0; c < C_FEAT; c++)
        w[c] = __ldg(reinterpret_cast<const float4*>(W + c * D_MODEL) + lane);
    float4 wb  = __ldg(reinterpret_cast<const float4*>(bias)  + lane);
    float4 wg  = __ldg(reinterpret_cast<const float4*>(gamma) + lane);
    float4 wbe = __ldg(reinterpret_cast<const float4*>(beta)  + lane);

    __syncthreads();

    int rbase = base + warp * ROWS_PER_WARP;
#pragma unroll 4
    for (int t = 0; t < ROWS_PER_WARP; t++) {
        int r = rbase + t;
        if (r >= rows) break;

        const float* srow = sRow + (warp * ROWS_PER_WARP + t) * C_FEAT;
        float sv0 = srow[0], sv1 = srow[1];

        // Stash packed xy for the edge kernel.
        if (lane == 0) {
            int b = (r >= n_nodes) ? 1 : 0;
            int n = r - b * n_nodes;
            if (n >= 0 && n < N_NODES) {
                float2* p = reinterpret_cast<float2*>(
                    reinterpret_cast<char*>(&g_xy[n]) + (size_t)b * 8);
                *p = make_float2(sv0, sv1);
            }
        }

        // GEMM: acc = bias + sum_c sv[c] * W[c][4*lane..4*lane+3]
        float4 acc = wb;
        {
            float s;
            s = sv0;
            acc.x = fmaf(s, w[0].x, acc.x); acc.y = fmaf(s, w[0].y, acc.y);
            acc.z = fmaf(s, w[0].z, acc.z); acc.w = fmaf(s, w[0].w, acc.w);
            s = sv1;
            acc.x = fmaf(s, w[1].x, acc.x); acc.y = fmaf(s, w[1].y, acc.y);
            acc.z = fmaf(s, w[1].z, acc.z); acc.w = fmaf(s, w[1].w, acc.w);
#pragma unroll
            for (int c = 2; c < C_FEAT; c++) {
                s = srow[c];
                acc.x = fmaf(s, w[c].x, acc.x); acc.y = fmaf(s, w[c].y, acc.y);
                acc.z = fmaf(s, w[c].z, acc.z); acc.w = fmaf(s, w[c].w, acc.w);
            }
        }

        float4 v;
        v.x = fast_gelu(acc.x); v.y = fast_gelu(acc.y);
        v.z = fast_gelu(acc.z); v.w = fast_gelu(acc.w);

        float sum   = v.x + v.y + v.z + v.w;
        float sumsq = v.x * v.x + v.y * v.y + v.z * v.z + v.w * v.w;
#pragma unroll
        for (int o = 16; o > 0; o >>= 1) {
            sum   += __shfl_xor_sync(0xFFFFFFFFu, sum, o);
            sumsq += __shfl_xor_sync(0xFFFFFFFFu, sumsq, o);
        }
        float mean = sum * (1.0f / D_MODEL);
        float var  = sumsq * (1.0f / D_MODEL) - mean * mean;
        float rstd = rsqrtf(var + LN_EPS);

        float4 o4;
        o4.x = fmaf((v.x - mean) * rstd, wg.x, wbe.x);
        o4.y = fmaf((v.y - mean) * rstd, wg.y, wbe.y);
        o4.z = fmaf((v.z - mean) * rstd, wg.z, wbe.z);
        o4.w = fmaf((v.w - mean) * rstd, wg.w, wbe.w);
        reinterpret_cast<float4*>(out + (size_t)r * D_MODEL)[lane] = o4;
    }
}

// ---------------------------------------------------------------------------
// Edge deterrence: one thread handles FOUR consecutive edges, BOTH batches.
//   det[b*E + e] = -0.5 * || xy[b*N + src[e]] - xy[b*N + dst[e]] ||^2
// Both batches' coords packed in one float4 -> 2 gathers per edge. Index
// dtype chosen at runtime via g_is32 (uniform branch). Indices clamped to
// [0, n_nodes) so a bad assumption yields rel_err, never an illegal access.
// ---------------------------------------------------------------------------
__global__ void __launch_bounds__(256) edge_kernel(
        const void* __restrict__ ei_raw,
        float* __restrict__ det, int E, int n_nodes) {
    int q = blockIdx.x * blockDim.x + threadIdx.x;
    int e = q * 4;
    if (e >= E) return;

    unsigned s[4], d[4];
    bool full = (e + 3 < E);
    if (full) {
        if (g_is32) {
            const int* p = (const int*)ei_raw;
            int4 a = __ldg(reinterpret_cast<const int4*>(p + e));
            int4 b = __ldg(reinterpret_cast<const int4*>(p + (size_t)E + e));
            s[0] = a.x; s[1] = a.y; s[2] = a.z; s[3] = a.w;
            d[0] = b.x; d[1] = b.y; d[2] = b.z; d[3] = b.w;
        } else {
            const long long* p = (const long long*)ei_raw;
            longlong2 a0 = __ldg(reinterpret_cast<const longlong2*>(p + e));
            longlong2 a1 = __ldg(reinterpret_cast<const longlong2*>(p + e + 2));
            longlong2 b0 = __ldg(reinterpret_cast<const longlong2*>(p + (size_t)E + e));
            longlong2 b1 = __ldg(reinterpret_cast<const longlong2*>(p + (size_t)E + e + 2));
            s[0] = (unsigned)a0.x; s[1] = (unsigned)a0.y;
            s[2] = (unsigned)a1.x; s[3] = (unsigned)a1.y;
            d[0] = (unsigned)b0.x; d[1] = (unsigned)b0.y;
            d[2] = (unsigned)b1.x; d[3] = (unsigned)b1.y;
        }
    } else {
#pragma unroll
        for (int k = 0; k < 4; k++) {
            if (e + k < E) {
                if (g_is32) {
                    const int* p = (const int*)ei_raw;
                    s[k] = (unsigned)__ldg(p + e + k);
                    d[k] = (unsigned)__ldg(p + (size_t)E + e + k);
                } else {
                    const long long* p = (const long long*)ei_raw;
                    s[k] = (unsigned)__ldg(p + e + k);
                    d[k] = (unsigned)__ldg(p + (size_t)E + e + k);
                }
            } else { s[k] = 0; d[k] = 0; }
        }
    }

    unsigned lim = (unsigned)(n_nodes - 1);
    float4 ps[4], pd[4];
#pragma unroll
    for (int k = 0; k < 4; k++) {
        ps[k] = __ldg(&g_xy[min(s[k], lim)]);
        pd[k] = __ldg(&g_xy[min(d[k], lim)]);
    }

    float r0[4], r1[4];
#pragma unroll
    for (int k = 0; k < 4; k++) {
        float dx0 = ps[k].x - pd[k].x, dy0 = ps[k].y - pd[k].y;
        float dx1 = ps[k].z - pd[k].z, dy1 = ps[k].w - pd[k].w;
        r0[k] = -0.5f * (dx0 * dx0 + dy0 * dy0);
        r1[k] = -0.5f * (dx1 * dx1 + dy1 * dy1);
    }

    if (full) {
        *reinterpret_cast<float4*>(det + e) =
            make_float4(r0[0], r0[1], r0[2], r0[3]);
        *reinterpret_cast<float4*>(det + (size_t)E + e) =
            make_float4(r1[0], r1[1], r1[2], r1[3]);
    } else {
#pragma unroll
        for (int k = 0; k < 4; k++) {
            if (e + k < E) {
                det[e + k] = r0[k];
                det[(size_t)E + e + k] = r1[k];
            }
        }
    }
}

// ---------------------------------------------------------------------------
// Launch. Inputs (metadata order): static, edge_index, fc_w, fc_b, ln_g, ln_b
// Output: [H0 flat (rows*128 f32)] ++ [det flat (2*E f32)]
// E derived from out_size: out_size = rows*128 + 2*E.
// ---------------------------------------------------------------------------
extern "C" void kernel_launch(void* const* d_in, const int* in_sizes, int n_in,
                              void* d_out, int out_size) {
    const float* x    = (const float*)d_in[0];
    const void*  ei   = d_in[1];
    const float* W    = (const float*)d_in[2];
    const float* bias = (const float*)d_in[3];
    const float* g    = (const float*)d_in[4];
    const float* be   = (const float*)d_in[5];

    int rows    = in_sizes[0] / C_FEAT;                    // B*N = 100000
    int n_nodes = rows / 2;                                // N = 50000 (B=2)
    long long detN = (long long)out_size - (long long)rows * D_MODEL; // B*E
    int E = (int)(detN / 2);                               // 1600000

    float* H0  = (float*)d_out;
    float* det = (float*)d_out + (size_t)rows * D_MODEL;

    // +1 block: the last block runs the index-dtype detector.
    int nblk = (rows + ROWS_PER_BLOCK - 1) / ROWS_PER_BLOCK + 1;
    encoder_kernel<<<nblk, 256>>>(x, (const int*)ei, W, bias, g, be, H0,
                                  rows, n_nodes);

    int nquad = (E + 3) / 4;                   // 4 edges per thread
    edge_kernel<<<(nquad + 255) / 256, 256>>>(ei, det, E, n_nodes);
}

// round 10
// speedup vs baseline: 1.4678x; 1.0091x over previous
#include <cuda_runtime.h>

#define D_MODEL 128
#define C_FEAT  16
#define LN_EPS  1e-5f
#define ROWS_PER_BLOCK 128
#define ROWS_PER_WARP  16

// Packed per-node xy for both batches: {x_b0, y_b0, x_b1, y_b1}.
// 50000 nodes * 16B = 800KB -> fully L2-resident gather table.
#define N_NODES 50000
__device__ float4 g_xy[N_NODES];

// Runtime-detected index dtype: 1 if edge_index buffer is int32, 0 if int64.
__device__ int g_is32;

// ---------------------------------------------------------------------------
// xy_pack: builds the packed gather table + runs the dtype detector.
// Thread i packs row r=i's (x,y) into g_xy[n] half b. The LAST block instead
// runs the index-dtype detector: genuine int64 indices < 50000 have all-zero
// high 32-bit words; int32-materialized data has random values there.
// ---------------------------------------------------------------------------
__global__ void __launch_bounds__(256) xy_pack_kernel(
        const float* __restrict__ x,
        const int*   __restrict__ ei32,
        int rows, int n_nodes) {
    if (blockIdx.x == gridDim.x - 1) {            // detector block
        if (threadIdx.x < 32) {
            int f = 0;
#pragma unroll
            for (int i = 0; i < 8; i++)
                f |= __ldg(ei32 + ((threadIdx.x * 8 + i) * 2 + 1));
            unsigned any = __ballot_sync(0xFFFFFFFFu, f != 0);
            if (threadIdx.x == 0) g_is32 = (any != 0) ? 1 : 0;
        }
        return;
    }
    int r = blockIdx.x * blockDim.x + threadIdx.x;
    if (r >= rows) return;
    float2 xy = __ldg(reinterpret_cast<const float2*>(x + (size_t)r * C_FEAT));
    int b = (r >= n_nodes) ? 1 : 0;
    int n = r - b * n_nodes;
    if (n >= 0 && n < N_NODES) {
        float2* p = reinterpret_cast<float2*>(
            reinterpret_cast<char*>(&g_xy[n]) + (size_t)b * 8);
        *p = xy;
    }
}

// ---------------------------------------------------------------------------
// Fast exact-enough GELU. erf via Abramowitz-Stegun 7.1.26 (|abs err|<=1.5e-7)
// gelu(x) = 0.5 x (1 + erf(x/sqrt2)) = 0.5 x + 0.5|x| erf(|x|/sqrt2)
// ---------------------------------------------------------------------------
__device__ __forceinline__ float fast_gelu(float x) {
    float ax = fabsf(x);
    float t = ax * 0.70710678118654752f;
    float k = __fdividef(1.0f, fmaf(0.3275911f, t, 1.0f));
    float p = fmaf(1.061405429f, k, -1.453152027f);
    p = fmaf(p, k, 1.421413741f);
    p = fmaf(p, k, -0.284496736f);
    p = fmaf(p, k, 0.254829592f);
    p *= k;
    float erfabs = 1.0f - p * __expf(-t * t);
    return fmaf(0.5f * ax, erfabs, 0.5f * x);
}

// ---------------------------------------------------------------------------
// Encoder block body: register-resident weights. Each lane owns 4 consecutive
// output channels d = 4*lane..4*lane+3, keeps W[:, d:d+4] in 16 float4
// registers; the warp loops over 16 rows. Per row: 16 smem broadcasts +
// reg-reg FMAs + GELU + warp-reduce LN + one STG.128.
// ---------------------------------------------------------------------------
__device__ __forceinline__ void encoder_block(
        int ebid,
        const float* __restrict__ x,
        const float* __restrict__ W,
        const float* __restrict__ bias,
        const float* __restrict__ gamma,
        const float* __restrict__ beta,
        float* __restrict__ out,
        int rows, float* sRow) {
    int base = ebid * ROWS_PER_BLOCK;
    {   // coalesced staging of this block's rows
        int gbase = base * C_FEAT;
        int total = rows * C_FEAT;
#pragma unroll
        for (int i = 0; i < ROWS_PER_BLOCK * C_FEAT / 256; i++) {
            int li = threadIdx.x + i * 256;
            int gi = gbase + li;
            sRow[li] = (gi < total) ? x[gi] : 0.f;
        }
    }

    int warp = threadIdx.x >> 5;
    int lane = threadIdx.x & 31;

    // Register-resident weights/affine params for channels 4*lane..4*lane+3.
    float4 w[C_FEAT];
#pragma unroll
    for (int c = 0; c < C_FEAT; c++)
        w[c] = __ldg(reinterpret_cast<const float4*>(W + c * D_MODEL) + lane);
    float4 wb  = __ldg(reinterpret_cast<const float4*>(bias)  + lane);
    float4 wg  = __ldg(reinterpret_cast<const float4*>(gamma) + lane);
    float4 wbe = __ldg(reinterpret_cast<const float4*>(beta)  + lane);

    __syncthreads();

    int rbase = base + warp * ROWS_PER_WARP;
#pragma unroll 4
    for (int t = 0; t < ROWS_PER_WARP; t++) {
        int r = rbase + t;
        if (r >= rows) break;

        const float* srow = sRow + (warp * ROWS_PER_WARP + t) * C_FEAT;

        // GEMM: acc = bias + sum_c sv[c] * W[c][4*lane..4*lane+3]
        float4 acc = wb;
#pragma unroll
        for (int c = 0; c < C_FEAT; c++) {
            float s = srow[c];
            acc.x = fmaf(s, w[c].x, acc.x); acc.y = fmaf(s, w[c].y, acc.y);
            acc.z = fmaf(s, w[c].z, acc.z); acc.w = fmaf(s, w[c].w, acc.w);
        }

        float4 v;
        v.x = fast_gelu(acc.x); v.y = fast_gelu(acc.y);
        v.z = fast_gelu(acc.z); v.w = fast_gelu(acc.w);

        float sum   = v.x + v.y + v.z + v.w;
        float sumsq = v.x * v.x + v.y * v.y + v.z * v.z + v.w * v.w;
#pragma unroll
        for (int o = 16; o > 0; o >>= 1) {
            sum   += __shfl_xor_sync(0xFFFFFFFFu, sum, o);
            sumsq += __shfl_xor_sync(0xFFFFFFFFu, sumsq, o);
        }
        float mean = sum * (1.0f / D_MODEL);
        float var  = sumsq * (1.0f / D_MODEL) - mean * mean;
        float rstd = rsqrtf(var + LN_EPS);

        float4 o4;
        o4.x = fmaf((v.x - mean) * rstd, wg.x, wbe.x);
        o4.y = fmaf((v.y - mean) * rstd, wg.y, wbe.y);
        o4.z = fmaf((v.z - mean) * rstd, wg.z, wbe.z);
        o4.w = fmaf((v.w - mean) * rstd, wg.w, wbe.w);
        reinterpret_cast<float4*>(out + (size_t)r * D_MODEL)[lane] = o4;
    }
}

// ---------------------------------------------------------------------------
// Edge block body: each thread handles FOUR consecutive edges, BOTH batches.
//   det[b*E + e] = -0.5 * || xy[b*N + src[e]] - xy[b*N + dst[e]] ||^2
// Both batches' coords packed in one float4 -> 2 gathers per edge. Index
// dtype chosen at runtime via g_is32 (uniform branch). Indices clamped to
// [0, n_nodes) so a bad assumption yields rel_err, never an illegal access.
// ---------------------------------------------------------------------------
__device__ __forceinline__ void edge_block(
        int gbid,
        const void* __restrict__ ei_raw,
        float* __restrict__ det, int E, int n_nodes) {
    int q = gbid * 256 + threadIdx.x;
    int e = q * 4;
    if (e >= E) return;

    unsigned s[4], d[4];
    bool full = (e + 3 < E);
    if (full) {
        if (g_is32) {
            const int* p = (const int*)ei_raw;
            int4 a = __ldg(reinterpret_cast<const int4*>(p + e));
            int4 b = __ldg(reinterpret_cast<const int4*>(p + (size_t)E + e));
            s[0] = a.x; s[1] = a.y; s[2] = a.z; s[3] = a.w;
            d[0] = b.x; d[1] = b.y; d[2] = b.z; d[3] = b.w;
        } else {
            const long long* p = (const long long*)ei_raw;
            longlong2 a0 = __ldg(reinterpret_cast<const longlong2*>(p + e));
            longlong2 a1 = __ldg(reinterpret_cast<const longlong2*>(p + e + 2));
            longlong2 b0 = __ldg(reinterpret_cast<const longlong2*>(p + (size_t)E + e));
            longlong2 b1 = __ldg(reinterpret_cast<const longlong2*>(p + (size_t)E + e + 2));
            s[0] = (unsigned)a0.x; s[1] = (unsigned)a0.y;
            s[2] = (unsigned)a1.x; s[3] = (unsigned)a1.y;
            d[0] = (unsigned)b0.x; d[1] = (unsigned)b0.y;
            d[2] = (unsigned)b1.x; d[3] = (unsigned)b1.y;
        }
    } else {
#pragma unroll
        for (int k = 0; k < 4; k++) {
            if (e + k < E) {
                if (g_is32) {
                    const int* p = (const int*)ei_raw;
                    s[k] = (unsigned)__ldg(p + e + k);
                    d[k] = (unsigned)__ldg(p + (size_t)E + e + k);
                } else {
                    const long long* p = (const long long*)ei_raw;
                    s[k] = (unsigned)__ldg(p + e + k);
                    d[k] = (unsigned)__ldg(p + (size_t)E + e + k);
                }
            } else { s[k] = 0; d[k] = 0; }
        }
    }

    unsigned lim = (unsigned)(n_nodes - 1);
    float4 ps[4], pd[4];
#pragma unroll
    for (int k = 0; k < 4; k++) {
        ps[k] = __ldg(&g_xy[min(s[k], lim)]);
        pd[k] = __ldg(&g_xy[min(d[k], lim)]);
    }

    float r0[4], r1[4];
#pragma unroll
    for (int k = 0; k < 4; k++) {
        float dx0 = ps[k].x - pd[k].x, dy0 = ps[k].y - pd[k].y;
        float dx1 = ps[k].z - pd[k].z, dy1 = ps[k].w - pd[k].w;
        r0[k] = -0.5f * (dx0 * dx0 + dy0 * dy0);
        r1[k] = -0.5f * (dx1 * dx1 + dy1 * dy1);
    }

    if (full) {
        *reinterpret_cast<float4*>(det + e) =
            make_float4(r0[0], r0[1], r0[2], r0[3]);
        *reinterpret_cast<float4*>(det + (size_t)E + e) =
            make_float4(r1[0], r1[1], r1[2], r1[3]);
    } else {
#pragma unroll
        for (int k = 0; k < 4; k++) {
            if (e + k < E) {
                det[e + k] = r0[k];
                det[(size_t)E + e + k] = r1[k];
            }
        }
    }
}

// ---------------------------------------------------------------------------
// Fused role-split kernel. Grid = 3 * nenc blocks, interleaved by bid % 3:
//   bid % 3 == 0 -> encoder block bid/3          (1/3 of blocks, 782 used)
//   bid % 3 != 0 -> edge block bid - bid/3 - 1   (2/3 of blocks, 1563 used)
// The interleave makes issue-bound encoder warps and L1-latency-bound edge
// warps co-resident on every SM from wave 0: edge memory latency hides under
// encoder issue pressure, so per-SM time ~ max(work types), not the sum.
// ---------------------------------------------------------------------------
__global__ void __launch_bounds__(256, 2) fused_kernel(
        const float* __restrict__ x,
        const void*  __restrict__ ei,
        const float* __restrict__ W,
        const float* __restrict__ bias,
        const float* __restrict__ gamma,
        const float* __restrict__ beta,
        float* __restrict__ H0,
        float* __restrict__ det,
        int rows, int E, int n_nodes, int nenc) {
    __shared__ float sRow[ROWS_PER_BLOCK * C_FEAT];   // 8KB (encoder role)
    int bid = blockIdx.x;
    int third = bid / 3;
    if (bid - third * 3 == 0) {
        if (third < nenc)
            encoder_block(third, x, W, bias, gamma, beta, H0, rows, sRow);
    } else {
        edge_block(bid - third - 1, ei, det, E, n_nodes);
    }
}

// ---------------------------------------------------------------------------
// Launch. Inputs (metadata order): static, edge_index, fc_w, fc_b, ln_g, ln_b
// Output: [H0 flat (rows*128 f32)] ++ [det flat (2*E f32)]
// E derived from out_size: out_size = rows*128 + 2*E. Single stream, no
// statics — fully graph-capturable.
// ---------------------------------------------------------------------------
extern "C" void kernel_launch(void* const* d_in, const int* in_sizes, int n_in,
                              void* d_out, int out_size) {
    const float* x    = (const float*)d_in[0];
    const void*  ei   = d_in[1];
    const float* W    = (const float*)d_in[2];
    const float* bias = (const float*)d_in[3];
    const float* g    = (const float*)d_in[4];
    const float* be   = (const float*)d_in[5];

    int rows    = in_sizes[0] / C_FEAT;                    // B*N = 100000
    int n_nodes = rows / 2;                                // N = 50000 (B=2)
    long long detN = (long long)out_size - (long long)rows * D_MODEL; // B*E
    int E = (int)(detN / 2);                               // 1600000

    float* H0  = (float*)d_out;
    float* det = (float*)d_out + (size_t)rows * D_MODEL;

    // 1) xy table + dtype detector (+1 detector block).
    int nxy = (rows + 255) / 256 + 1;
    xy_pack_kernel<<<nxy, 256>>>(x, (const int*)ei, rows, n_nodes);

    // 2) fused encoder+edge, role-interleaved.
    int nenc  = (rows + ROWS_PER_BLOCK - 1) / ROWS_PER_BLOCK;   // 782
    int nquad = (E + 3) / 4;                                    // 400000
    int nedge = (nquad + 255) / 256;                            // 1563
    // grid must cover: nenc mod-0 slots and nedge non-mod-0 slots.
    int grid_a = 3 * nenc;            // provides nenc enc + 2*nenc edge slots
    int grid_b = nedge + (nedge + 1) / 2 + 1;  // enough non-mod0 slots
    int grid = (grid_a > grid_b) ? grid_a : grid_b;
    fused_kernel<<<grid, 256>>>(x, ei, W, bias, g, be, H0, det,
                                rows, E, n_nodes, nenc);
}